// round 12
// baseline (speedup 1.0000x reference)
#include <cuda_runtime.h>
#include <cuda_bf16.h>
#include <cstdint>

#define BATCH 8
#define CIN 256
#define COUT 128
#define HIN 60
#define WIN 80
#define HUP 122
#define HOUT 120
#define WOUT 160
#define NPIX (HOUT*WOUT)   // 19200

// ---------------------------------------------------------------------------
// Device-global scratch
// ---------------------------------------------------------------------------
__device__ __align__(16) uint32_t      g_dwp[(size_t)BATCH * CIN * NPIX]; // packed bf16 hi<<16|lo, [b][c][p]
__device__ __align__(16) __nv_bfloat16 g_Ah[COUT * CIN];                  // pw hi [o][c]
__device__ __align__(16) __nv_bfloat16 g_Al[COUT * CIN];                  // pw lo [o][c]

// ---------------------------------------------------------------------------
// Kernel: split pointwise weights [o][c] fp32 -> bf16 hi/lo
// ---------------------------------------------------------------------------
__global__ void pwsplit_kernel(const float* __restrict__ pw) {
    int i = blockIdx.x * 256 + threadIdx.x;
    float v = pw[i];
    __nv_bfloat16 h = __float2bfloat16(v);
    __nv_bfloat16 l = __float2bfloat16(v - __bfloat162float(h));
    g_Ah[i] = h;
    g_Al[i] = l;
}

// ---------------------------------------------------------------------------
// Kernel: bilinear upsample + 3x3 depthwise (R6 structure; packed bf16 store)
// ---------------------------------------------------------------------------
__global__ __launch_bounds__(256) void dw_kernel(const float* __restrict__ x,
                                                 const float* __restrict__ wdw) {
    __shared__ float vs[HUP * WIN];                  // 39040 B

    int bc = blockIdx.x;
    int c  = bc & (CIN - 1);
    const float* xp = x + (size_t)bc * (HIN * WIN);
    uint32_t* op = g_dwp + (size_t)bc * NPIX;
    int tid = threadIdx.x;

    const float SY = (float)(59.0 / 121.0);
    const float SX = (float)(79.0 / 161.0);

    for (int i = tid; i < HUP * WIN; i += 256) {
        int rr = i / WIN;
        int xc = i - rr * WIN;
        float hy  = rr * SY;
        float y0f = floorf(hy);
        int   y0  = (int)y0f;
        float fy  = hy - y0f;
        int   y1  = y0 + 1; if (y1 > HIN - 1) y1 = HIN - 1;
        float a  = xp[y0 * WIN + xc];
        float b2 = xp[y1 * WIN + xc];
        vs[i] = a + fy * (b2 - a);
    }

    float kd[9];
#pragma unroll
    for (int t = 0; t < 9; t++) kd[t] = __ldg(wdw + c * 9 + t);

    __syncthreads();

    for (int s = tid; s < 2400; s += 256) {
        int h  = s / 20;
        int w0 = (s - h * 20) * 8;

        float u[3][10];
#pragma unroll
        for (int j = 0; j < 10; j++) {
            int   cc  = w0 + j;
            float wx  = cc * SX;
            float x0f = floorf(wx);
            int   x0  = (int)x0f;
            float fx  = wx - x0f;
            int   x1  = x0 + 1; if (x1 > WIN - 1) x1 = WIN - 1;
#pragma unroll
            for (int i2 = 0; i2 < 3; i2++) {
                const float* vr = vs + (h + i2) * WIN;
                float a  = vr[x0];
                float b2 = vr[x1];
                u[i2][j] = a + fx * (b2 - a);
            }
        }

        uint32_t rp[8];
#pragma unroll
        for (int ww = 0; ww < 8; ww++) {
            float acc = 0.0f;
#pragma unroll
            for (int i2 = 0; i2 < 3; i2++)
#pragma unroll
                for (int j = 0; j < 3; j++)
                    acc = fmaf(kd[i2 * 3 + j], u[i2][ww + j], acc);
            __nv_bfloat16 hh = __float2bfloat16(acc);
            __nv_bfloat16 ll = __float2bfloat16(acc - __bfloat162float(hh));
            rp[ww] = ((uint32_t)__bfloat16_as_ushort(hh) << 16) |
                      (uint32_t)__bfloat16_as_ushort(ll);
        }

        uint4* dst = (uint4*)(op + h * WOUT + w0);
        dst[0] = make_uint4(rp[0], rp[1], rp[2], rp[3]);
        dst[1] = make_uint4(rp[4], rp[5], rp[6], rp[7]);
    }
}

// ---------------------------------------------------------------------------
// GEMM: mma.sync split-bf16 3-pass, packed-B PRMT fragments,
// cp.async double-buffered smem (no staging registers).
// Block 128(o) x 128(p), 8 warps, warp tile 64x32, K chunks of 32.
// ---------------------------------------------------------------------------
#define APAD 40      // A row stride (bf16): 80 B
#define BPADu 132    // B row stride (u32): 528 B
#define AB_BYTES (128 * APAD * 2)        // 10240 per A array per buffer
#define BB_BYTES (32 * BPADu * 4)        // 16896 per B buffer
#define GEMM_SMEM (4 * AB_BYTES + 2 * BB_BYTES)   // 74752 B

__device__ __forceinline__ uint32_t smem_u32(const void* p) {
    uint32_t a;
    asm("{ .reg .u64 t; cvta.to.shared.u64 t, %1; cvt.u32.u64 %0, t; }" : "=r"(a) : "l"(p));
    return a;
}
__device__ __forceinline__ void cp16(uint32_t dst, const void* src) {
    asm volatile("cp.async.cg.shared.global [%0], [%1], 16;" :: "r"(dst), "l"(src));
}
__device__ __forceinline__ void mma_bf16(float* d, const uint32_t* a, const uint32_t* b) {
    asm volatile(
        "mma.sync.aligned.m16n8k16.row.col.f32.bf16.bf16.f32 "
        "{%0,%1,%2,%3}, {%4,%5,%6,%7}, {%8,%9}, {%0,%1,%2,%3};"
        : "+f"(d[0]), "+f"(d[1]), "+f"(d[2]), "+f"(d[3])
        : "r"(a[0]), "r"(a[1]), "r"(a[2]), "r"(a[3]), "r"(b[0]), "r"(b[1]));
}

__global__ __launch_bounds__(256) void gemm_kernel(float* __restrict__ out) {
    extern __shared__ char smem[];
    // layout: Ah[2] | Al[2] | B[2]
    uint32_t sAh = smem_u32(smem);
    uint32_t sAl = sAh + 2 * AB_BYTES;
    uint32_t sB  = sAh + 4 * AB_BYTES;

    int tid  = threadIdx.x;
    int lane = tid & 31;
    int wid  = tid >> 5;

    int b  = blockIdx.x / (NPIX / 128);
    int p0 = (blockIdx.x - b * (NPIX / 128)) * 128;

    const char* srcB = (const char*)(g_dwp + (size_t)b * CIN * NPIX + p0);

    int mw = (wid >> 2) * 64;
    int nw = (wid & 3) * 32;
    int g  = lane >> 2;
    int q  = lane & 3;

    // loader decomposition
    int rowA = tid >> 1;                             // 0..127
    int segA = (tid & 1) * 2;                        // 2 segs of 16B each (0,2)
    int rowB = tid >> 3;                             // 0..31
    int segB = (tid & 7) * 4;                        // 4 segs of 16B each

    float acc[4][4][4];
#pragma unroll
    for (int i = 0; i < 4; i++)
#pragma unroll
        for (int j = 0; j < 4; j++)
#pragma unroll
            for (int k = 0; k < 4; k++) acc[i][j][k] = 0.0f;

    // --- async chunk loader (raw copies; no conversion) ---
    auto load_chunk = [&](int ck, int buf) {
        uint32_t dAh = sAh + buf * AB_BYTES + rowA * (APAD * 2) + segA * 16;
        uint32_t dAl = sAl + buf * AB_BYTES + rowA * (APAD * 2) + segA * 16;
        const char* gA = (const char*)g_Ah + (size_t)rowA * 512 + ck * 64 + segA * 16;
        const char* gL = (const char*)g_Al + (size_t)rowA * 512 + ck * 64 + segA * 16;
        cp16(dAh,      gA);
        cp16(dAh + 16, gA + 16);
        cp16(dAl,      gL);
        cp16(dAl + 16, gL + 16);
        uint32_t dB = sB + buf * BB_BYTES + rowB * (BPADu * 4) + segB * 16;
        const char* gB = srcB + (size_t)(ck * 32 + rowB) * (NPIX * 4) + segB * 16;
#pragma unroll
        for (int i2 = 0; i2 < 4; i2++)
            cp16(dB + i2 * 16, gB + i2 * 16);
    };

    load_chunk(0, 0);
    asm volatile("cp.async.commit_group;");

    for (int ck = 0; ck < CIN / 32; ++ck) {
        int buf = ck & 1;
        if (ck + 1 < CIN / 32) {
            load_chunk(ck + 1, buf ^ 1);
            asm volatile("cp.async.commit_group;");
            asm volatile("cp.async.wait_group 1;");
        } else {
            asm volatile("cp.async.wait_group 0;");
        }
        __syncthreads();

        uint32_t aH = sAh + buf * AB_BYTES;
        uint32_t aL = sAl + buf * AB_BYTES;
        const uint32_t* Bb = (const uint32_t*)(smem + 4 * AB_BYTES + buf * BB_BYTES);
        const __nv_bfloat16* AH = (const __nv_bfloat16*)(smem + buf * AB_BYTES);
        const __nv_bfloat16* AL = (const __nv_bfloat16*)(smem + 2 * AB_BYTES + buf * AB_BYTES);

#pragma unroll
        for (int kk = 0; kk < 32; kk += 16) {
            int k0 = kk + q * 2;

            // B fragments: packed word -> PRMT split into hi/lo bf16x2
            uint32_t bh[4][2], bl[4][2];
#pragma unroll
            for (int nt = 0; nt < 4; nt++) {
                int n = nw + nt * 8 + g;
                uint32_t w0 = Bb[k0 * BPADu + n];
                uint32_t w1 = Bb[(k0 + 1) * BPADu + n];
                bh[nt][0] = __byte_perm(w0, w1, 0x7632);
                bl[nt][0] = __byte_perm(w0, w1, 0x5410);
                uint32_t w2 = Bb[(k0 + 8) * BPADu + n];
                uint32_t w3 = Bb[(k0 + 9) * BPADu + n];
                bh[nt][1] = __byte_perm(w2, w3, 0x7632);
                bl[nt][1] = __byte_perm(w2, w3, 0x5410);
            }

            // A-hi fragments
            uint32_t ah[4][4];
#pragma unroll
            for (int mt = 0; mt < 4; mt++) {
                int m = mw + mt * 16 + g;
                ah[mt][0] = *(const uint32_t*)&AH[m * APAD + k0];
                ah[mt][1] = *(const uint32_t*)&AH[(m + 8) * APAD + k0];
                ah[mt][2] = *(const uint32_t*)&AH[m * APAD + k0 + 8];
                ah[mt][3] = *(const uint32_t*)&AH[(m + 8) * APAD + k0 + 8];
            }

#pragma unroll
            for (int mt = 0; mt < 4; mt++)
#pragma unroll
                for (int nt = 0; nt < 4; nt++)
                    mma_bf16(acc[mt][nt], ah[mt], bh[nt]);

            uint32_t al[4][4];
#pragma unroll
            for (int mt = 0; mt < 4; mt++) {
                int m = mw + mt * 16 + g;
                al[mt][0] = *(const uint32_t*)&AL[m * APAD + k0];
                al[mt][1] = *(const uint32_t*)&AL[(m + 8) * APAD + k0];
                al[mt][2] = *(const uint32_t*)&AL[m * APAD + k0 + 8];
                al[mt][3] = *(const uint32_t*)&AL[(m + 8) * APAD + k0 + 8];
            }
#pragma unroll
            for (int mt = 0; mt < 4; mt++)
#pragma unroll
                for (int nt = 0; nt < 4; nt++)
                    mma_bf16(acc[mt][nt], al[mt], bh[nt]);

#pragma unroll
            for (int mt = 0; mt < 4; mt++)
#pragma unroll
                for (int nt = 0; nt < 4; nt++)
                    mma_bf16(acc[mt][nt], ah[mt], bl[nt]);
        }
        __syncthreads();                             // buffer reuse barrier
        (void)aH; (void)aL;
    }

    // --- epilogue ---
    float* base = out + (size_t)b * COUT * NPIX + p0;
#pragma unroll
    for (int mt = 0; mt < 4; mt++) {
#pragma unroll
        for (int nt = 0; nt < 4; nt++) {
            int m = mw + mt * 16 + g;
            int n = nw + nt * 8 + q * 2;
            *(float2*)&base[(size_t)m * NPIX + n] =
                make_float2(acc[mt][nt][0], acc[mt][nt][1]);
            *(float2*)&base[(size_t)(m + 8) * NPIX + n] =
                make_float2(acc[mt][nt][2], acc[mt][nt][3]);
        }
    }
}

// ---------------------------------------------------------------------------
// Launch
// ---------------------------------------------------------------------------
extern "C" void kernel_launch(void* const* d_in, const int* in_sizes, int n_in,
                              void* d_out, int out_size) {
    const float* x   = (const float*)d_in[0];   // [8,256,60,80]
    const float* wdw = (const float*)d_in[1];   // [256,1,3,3]
    const float* wpw = (const float*)d_in[2];   // [128,256]
    float* out = (float*)d_out;                 // [8,128,120,160]

    cudaFuncSetAttribute(gemm_kernel, cudaFuncAttributeMaxDynamicSharedMemorySize, GEMM_SMEM);

    pwsplit_kernel<<<128, 256>>>(wpw);
    dw_kernel<<<BATCH * CIN, 256>>>(x, wdw);
    gemm_kernel<<<BATCH * (NPIX / 128), 256, GEMM_SMEM>>>(out);
}